// round 17
// baseline (speedup 1.0000x reference)
#include <cuda_runtime.h>
#include <cuda_fp16.h>

#define MAXN   200000
#define CIN    32
#define HID    192
#define KOFF   9
#define COUT   32
#define EPSV   1e-5f

// fp16 scratch: expanded activations x1 = relu6(bn1(feats@W1)) [N,192].
// 76.8MB -> largely L2-resident (126MB L2); dw+proj fused so no z stream.
__device__ __half g_x1[(size_t)MAXN * HID];

// constants produced by k_expand block 0 for k_dwproj (next launch):
__device__ unsigned g_W3f[4 * 12 * 2 * 32];   // [j][s][i][lane] fragments
__device__ __align__(16) __half g_W2h[KOFF * HID];  // s2-folded W2, fp16
__device__ __align__(16) __half g_c2h[HID];         // folded BN2 offset
__device__ float g_s3[COUT], g_c3[COUT];            // folded BN3

__device__ __forceinline__ float relu6f(float x) {
    return fminf(fmaxf(x, 0.0f), 6.0f);
}
__device__ __forceinline__ unsigned int f2toh2(float a, float b) {
    __half2 h = __floats2half2_rn(a, b);
    return *reinterpret_cast<unsigned int*>(&h);
}
__device__ __forceinline__ unsigned int packh(__half lo, __half hi) {
    __half2 h = __halves2half2(lo, hi);
    return *reinterpret_cast<unsigned int*>(&h);
}
__device__ __forceinline__ __half2 u2h2(unsigned u) {
    return *reinterpret_cast<__half2*>(&u);
}
__device__ __forceinline__ unsigned h2u(__half2 h) {
    return *reinterpret_cast<unsigned*>(&h);
}

// m16n8k16 fp16 x fp16 -> fp32 MMA
__device__ __forceinline__ void mma16816(
    float& d0, float& d1, float& d2, float& d3,
    unsigned a0, unsigned a1, unsigned a2, unsigned a3,
    unsigned b0, unsigned b1)
{
    asm volatile(
        "mma.sync.aligned.m16n8k16.row.col.f32.f16.f16.f32 "
        "{%0,%1,%2,%3}, {%4,%5,%6,%7}, {%8,%9}, {%0,%1,%2,%3};\n"
        : "+f"(d0), "+f"(d1), "+f"(d2), "+f"(d3)
        : "r"(a0), "r"(a1), "r"(a2), "r"(a3), "r"(b0), "r"(b1));
}

// ldmatrix x4: full m16n8k16 A fragment in one instruction.
__device__ __forceinline__ void ldsm_x4(
    unsigned& r0, unsigned& r1, unsigned& r2, unsigned& r3, unsigned addr)
{
    asm volatile(
        "ldmatrix.sync.aligned.m8n8.x4.shared.b16 {%0,%1,%2,%3}, [%4];\n"
        : "=r"(r0), "=r"(r1), "=r"(r2), "=r"(r3) : "r"(addr));
}

// ---------------------------------------------------------------------------
// Kernel 1 (MMA): expand 1x1 conv + BN1 + relu6 -> g_x1 (fp16)
// Block = 768 thr = 24 warps; warp w owns output cols [8w, 8w+8).
// W1 fragments + BN1 fold built inline. Block 0 additionally packs all
// k_dwproj constants (W3f, s2-folded W2h, c2h, BN3).
// ---------------------------------------------------------------------------
#define FST   40    // feats smem row stride (halves)
#define XST   208   // epilogue smem stride (halves) = 26 uint4

__global__ void __launch_bounds__(768) k_expand(
    const float* __restrict__ feats,
    const float* __restrict__ W1, const float* __restrict__ W2,
    const float* __restrict__ W3,
    const float* __restrict__ g1, const float* __restrict__ b1,
    const float* __restrict__ m1, const float* __restrict__ v1,
    const float* __restrict__ g2, const float* __restrict__ b2,
    const float* __restrict__ m2, const float* __restrict__ v2,
    const float* __restrict__ g3, const float* __restrict__ b3,
    const float* __restrict__ m3, const float* __restrict__ v3,
    int N)
{
    __shared__ __align__(16) __half sf[64 * FST];
    __shared__ __align__(16) __half sx[64 * XST];

    const int tid  = threadIdx.x;
    const int w    = tid >> 5;
    const int lane = tid & 31;
    const int g    = lane >> 2;
    const int t    = lane & 3;
    const int colb = w * 8;
    const int c0   = colb + 2 * t;
    const int c1   = c0 + 1;

    // ---- block 0: pack dwproj constants (independent extra duty) ----
    if (blockIdx.x == 0) {
        if (tid < 128) {            // W3 fragments: j = tid>>5
            const int j = tid >> 5;
            const int col = j * 8 + g;
#pragma unroll
            for (int s = 0; s < 12; s++)
#pragma unroll
                for (int i = 0; i < 2; i++) {
                    const int k0 = 16 * s + 2 * t + 8 * i;
                    g_W3f[((j * 12 + s) * 2 + i) * 32 + lane] =
                        packh(__float2half(W3[(k0)     * COUT + col]),
                              __float2half(W3[(k0 + 1) * COUT + col]));
                }
        }
        // s2-folded W2 -> half
        for (int i = tid; i < KOFF * HID; i += 768) {
            const int ch = i % HID;
            const float s2 = g2[ch] * rsqrtf(v2[ch] + EPSV);
            g_W2h[i] = __float2half(W2[i] * s2);
        }
        if (tid < HID) {            // folded BN2 offset
            const float s2 = g2[tid] * rsqrtf(v2[tid] + EPSV);
            g_c2h[tid] = __float2half(b2[tid] - m2[tid] * s2);
        }
        if (tid < COUT) {           // BN3 fold
            const float s3 = g3[tid] * rsqrtf(v3[tid] + EPSV);
            g_s3[tid] = s3; g_c3[tid] = b3[tid] - m3[tid] * s3;
        }
    }

    // ---- inline W1 fragments + BN1 fold ----
    unsigned bf[2][2];
#pragma unroll
    for (int s = 0; s < 2; s++) {
        const int col = colb + g;
        const int k0 = 16 * s + 2 * t;
        bf[s][0] = packh(__float2half(W1[(k0)     * HID + col]),
                         __float2half(W1[(k0 + 1) * HID + col]));
        bf[s][1] = packh(__float2half(W1[(k0 + 8) * HID + col]),
                         __float2half(W1[(k0 + 9) * HID + col]));
    }
    const float s_a = g1[c0] * rsqrtf(v1[c0] + EPSV);
    const float o_a = b1[c0] - m1[c0] * s_a;
    const float s_b = g1[c1] * rsqrtf(v1[c1] + EPSV);
    const float o_b = b1[c1] - m1[c1] * s_b;

    const int r0 = blockIdx.x * 64;

    // ---- vectorized staging: 512 float4 loads, STS.64 stores ----
    if (tid < 512) {
        const int r  = tid >> 3;          // 0..63
        const int c4 = tid & 7;           // float4 index in row
        const int row = r0 + r;
        float4 f = make_float4(0.f, 0.f, 0.f, 0.f);
        if (row < N)
            f = *reinterpret_cast<const float4*>(feats + row * CIN + c4 * 4);
        uint2 h;
        h.x = f2toh2(f.x, f.y);
        h.y = f2toh2(f.z, f.w);
        *reinterpret_cast<uint2*>(sf + r * FST + c4 * 4) = h;
    }
    __syncthreads();

    // ldmatrix lane address: rows (lane>>3&1)*8+(lane&7), col (lane>>4)*8
    const int lrow = ((lane >> 3) & 1) * 8 + (lane & 7);
    const int lcol = (lane >> 4) * 8;
    const unsigned sfu =
        (unsigned)__cvta_generic_to_shared(sf) + (lrow * FST + lcol) * 2;

#pragma unroll
    for (int sub = 0; sub < 4; sub++) {
        float d0 = 0.f, d1 = 0.f, d2 = 0.f, d3 = 0.f;
        const unsigned abase = sfu + sub * 16 * FST * 2;
#pragma unroll
        for (int s = 0; s < 2; s++) {
            unsigned a0, a1, a2, a3;
            ldsm_x4(a0, a1, a2, a3, abase + s * 32);
            mma16816(d0, d1, d2, d3, a0, a1, a2, a3, bf[s][0], bf[s][1]);
        }
        const int rlo = sub * 16 + g;
        const int rhi = rlo + 8;
        *reinterpret_cast<unsigned*>(sx + rlo * XST + c0) =
            f2toh2(relu6f(fmaf(d0, s_a, o_a)), relu6f(fmaf(d1, s_b, o_b)));
        *reinterpret_cast<unsigned*>(sx + rhi * XST + c0) =
            f2toh2(relu6f(fmaf(d2, s_a, o_a)), relu6f(fmaf(d3, s_b, o_b)));
    }
    __syncthreads();

    // coalesced store: 64 rows x 24 uint4
    uint4* xg = reinterpret_cast<uint4*>(g_x1);
    const uint4* sxb = reinterpret_cast<const uint4*>(sx);
#pragma unroll
    for (int i = tid; i < 64 * 24; i += 768) {
        const int r = i / 24, ch = i % 24;
        const int row = r0 + r;
        if (row < N) xg[(size_t)row * 24 + ch] = sxb[r * 26 + ch];
    }
}

// ---------------------------------------------------------------------------
// Kernel 2 (FUSED): depthwise gather + relu6 -> smem tile -> project MMA +
// BN3 + residual -> out (fp32).
//
// Gather phase: thread = (row-group, 4-channel uint2 chunk). 48 chunks x 8
// row-groups = 384 threads, 48-row tile, 6 rows/thread. W2 taps (9 uint2)
// and c2 live in REGISTERS, loaded once per thread from L2-resident global —
// no W2 smem staging, no nbr smem tile, no pre-sync. Per-row L1tex cost
// drops ~45% vs the per-item smem-W2 design. 48 consecutive uint2 lanes
// cover one 384B x1 row = 3 lines; every warp-gather = 2 wavefronts.
//
// MMA phase: 12 warps = 4 n-tiles x 3 row-subtiles; ZST=200 bank-clean.
// ---------------------------------------------------------------------------
#define ZST    200   // halves; ldmatrix bank-clean (4r mod 32)
#define DWROWS 48

__global__ void __launch_bounds__(384, 2) k_dwproj(
    const int* __restrict__ nbr,
    const float* __restrict__ feats, float* __restrict__ out, int N)
{
    __shared__ __align__(16) __half zs[DWROWS * ZST];   // 19.2 KB

    const int tid  = threadIdx.x;
    const int lane = tid & 31;
    const int w    = tid >> 5;
    const int r0   = blockIdx.x * DWROWS;

    // ---- gather phase: fixed 4-channel chunk per thread ----
    const int rgrp = tid / 48;          // 0..7 row-group
    const int c4   = tid % 48;          // uint2 chunk
    const int hb   = c4 * 4;            // first channel (half index)

    // W2 taps (s2-folded) + c2 offset in registers, from L2-resident global
    uint2 wv[KOFF];
#pragma unroll
    for (int k = 0; k < KOFF; k++)
        wv[k] = *reinterpret_cast<const uint2*>(g_W2h + k * HID + hb);
    const uint2 cini = *reinterpret_cast<const uint2*>(g_c2h + hb);

    const __half2 zero2 = __floats2half2_rn(0.f, 0.f);
    const __half2 six2  = __floats2half2_rn(6.f, 6.f);

#pragma unroll
    for (int rr = 0; rr < 6; rr++) {
        const int rloc = rgrp * 6 + rr;
        const int row  = r0 + rloc;
        if (row < N) {
            int ids[KOFF];
#pragma unroll
            for (int k = 0; k < KOFF; k++) ids[k] = nbr[row * KOFF + k];

            uint2 v[KOFF];
#pragma unroll
            for (int k = 0; k < KOFF; k++) {
                v[k] = make_uint2(0u, 0u);
                if (ids[k] >= 0)
                    v[k] = *reinterpret_cast<const uint2*>(
                        g_x1 + (size_t)ids[k] * HID + hb);
            }

            __half2 a0 = u2h2(cini.x), a1 = u2h2(cini.y);
#pragma unroll
            for (int k = 0; k < KOFF; k++) {
                a0 = __hfma2(u2h2(v[k].x), u2h2(wv[k].x), a0);
                a1 = __hfma2(u2h2(v[k].y), u2h2(wv[k].y), a1);
            }
            uint2 o;
            o.x = h2u(__hmin2(six2, __hmax2(zero2, a0)));
            o.y = h2u(__hmin2(six2, __hmax2(zero2, a1)));
            *reinterpret_cast<uint2*>(zs + rloc * ZST + hb) = o;
        }
    }

    // ---- project MMA + BN3 + residual ----
    const int g  = lane >> 2;
    const int t  = lane & 3;
    const int j  = w & 3;                  // n-tile (12 warps: 4 x 3)
    const int rs = w >> 2;                 // row subtile 0..2
    const int c0 = 8 * j + 2 * t;

    unsigned bf[12][2];
#pragma unroll
    for (int s = 0; s < 12; s++) {
        bf[s][0] = g_W3f[((j * 12 + s) * 2 + 0) * 32 + lane];
        bf[s][1] = g_W3f[((j * 12 + s) * 2 + 1) * 32 + lane];
    }
    const float2 sv = *reinterpret_cast<const float2*>(g_s3 + c0);
    const float2 cv = *reinterpret_cast<const float2*>(g_c3 + c0);
    __syncthreads();

    const int lrow = ((lane >> 3) & 1) * 8 + (lane & 7);
    const int lcol = (lane >> 4) * 8;
    const unsigned zsu = (unsigned)__cvta_generic_to_shared(zs) +
                         ((rs * 16 + lrow) * ZST + lcol) * 2;

    float d0 = 0.f, d1 = 0.f, d2 = 0.f, d3 = 0.f;
#pragma unroll
    for (int s = 0; s < 12; s++) {
        unsigned a0, a1, a2, a3;
        ldsm_x4(a0, a1, a2, a3, zsu + s * 32);
        mma16816(d0, d1, d2, d3, a0, a1, a2, a3, bf[s][0], bf[s][1]);
    }

    const int rlo = r0 + rs * 16 + g;
    const int rhi = rlo + 8;
    if (rlo < N) {
        const float2 fi = *reinterpret_cast<const float2*>(feats + rlo * COUT + c0);
        float2 o;
        o.x = fmaf(d0, sv.x, cv.x) + fi.x;
        o.y = fmaf(d1, sv.y, cv.y) + fi.y;
        *reinterpret_cast<float2*>(out + rlo * COUT + c0) = o;
    }
    if (rhi < N) {
        const float2 fi = *reinterpret_cast<const float2*>(feats + rhi * COUT + c0);
        float2 o;
        o.x = fmaf(d2, sv.x, cv.x) + fi.x;
        o.y = fmaf(d3, sv.y, cv.y) + fi.y;
        *reinterpret_cast<float2*>(out + rhi * COUT + c0) = o;
    }
}

// ---------------------------------------------------------------------------
extern "C" void kernel_launch(void* const* d_in, const int* in_sizes, int n_in,
                              void* d_out, int out_size)
{
    const float* feats = (const float*)d_in[0];
    const int*   nbr   = (const int*)  d_in[1];
    const float* W1    = (const float*)d_in[2];
    const float* W2    = (const float*)d_in[3];
    const float* W3    = (const float*)d_in[4];
    const float* g1 = (const float*)d_in[5],  *b1 = (const float*)d_in[6];
    const float* m1 = (const float*)d_in[7],  *v1 = (const float*)d_in[8];
    const float* g2 = (const float*)d_in[9],  *b2 = (const float*)d_in[10];
    const float* m2 = (const float*)d_in[11], *v2 = (const float*)d_in[12];
    const float* g3 = (const float*)d_in[13], *b3 = (const float*)d_in[14];
    const float* m3 = (const float*)d_in[15], *v3 = (const float*)d_in[16];
    float* out = (float*)d_out;

    int N = in_sizes[0] / CIN;
    if (N > MAXN) N = MAXN;

    // K1: expand (MMA) — block 0 also packs dwproj constants
    const int tiles1 = (N + 63) / 64;
    k_expand<<<tiles1, 768>>>(feats, W1, W2, W3,
                              g1, b1, m1, v1, g2, b2, m2, v2,
                              g3, b3, m3, v3, N);

    // K2: fused depthwise gather (reg-cached W2) + project (MMA) + residual
    const int tiles2 = (N + DWROWS - 1) / DWROWS;
    k_dwproj<<<tiles2, 384>>>(nbr, feats, out, N);
}